// round 1
// baseline (speedup 1.0000x reference)
#include <cuda_runtime.h>

// out[b, s, d] = in[b, s, d] + PE[s, d]
// PE[s, 2i]   = sin(s / 10000^(2i/1024))
// PE[s, 2i+1] = cos(s / 10000^(2i/1024))
//
// B=8, S=4096, D=1024, fp32. Pure streaming: 268 MB HBM traffic.
// Each thread owns one float4 of one PE row (dims [4t, 4t+4) of row `pos`),
// computes the PE values once in registers (2x sincosf), then streams the
// 8 batch copies through it. PE transcendental cost is amortized 8x and
// fully hidden under the HBM stream.

#define SEQ_LEN 4096
#define D_MODEL 1024
#define BATCH   8
#define THREADS 256   // 256 threads * float4 = 1024 floats = one row

__global__ void __launch_bounds__(THREADS, 8)
pe_add_kernel(const float4* __restrict__ in, float4* __restrict__ out) {
    const int pos = blockIdx.x;        // 0..4095  (sequence position)
    const int t   = threadIdx.x;       // 0..255   (float4 index within row)

    // This thread's float4 covers dims {4t, 4t+1, 4t+2, 4t+3}
    //  = pairs i0 = 2t (dims 4t, 4t+1) and i1 = 2t+1 (dims 4t+2, 4t+3).
    // denom = 10000^(2i/1024) computed as exp2((2i/1024) * log2(10000)),
    // matching the reference's fp32 pow. 2i/1024 is exact (pow-of-2 denom).
    const float LOG2_10000 = 13.287712379549449f;
    const float fpos = (float)pos;

    float e0 = (float)(4 * t)     * (1.0f / 1024.0f);
    float e1 = (float)(4 * t + 2) * (1.0f / 1024.0f);
    float d0 = exp2f(e0 * LOG2_10000);
    float d1 = exp2f(e1 * LOG2_10000);
    float a0 = fpos / d0;
    float a1 = fpos / d1;

    float s0, c0, s1, c1;
    sincosf(a0, &s0, &c0);   // accurate variant: angles up to ~4095 rad
    sincosf(a1, &s1, &c1);

    const float4 pe = make_float4(s0, c0, s1, c1);

    // Stream 8 batches through this thread's PE float4.
    // Element offset of (b, pos, 4t) in float4 units:
    //   (b*SEQ_LEN + pos) * (D_MODEL/4) + t
    const int row_f4 = D_MODEL / 4;                  // 256
    long base = (long)pos * row_f4 + t;
    const long batch_stride = (long)SEQ_LEN * row_f4; // 1,048,576 float4s

#pragma unroll
    for (int b = 0; b < BATCH; ++b) {
        long idx = base + (long)b * batch_stride;
        float4 v = in[idx];
        v.x += pe.x;
        v.y += pe.y;
        v.z += pe.z;
        v.w += pe.w;
        out[idx] = v;
    }
}

extern "C" void kernel_launch(void* const* d_in, const int* in_sizes, int n_in,
                              void* d_out, int out_size) {
    const float4* in  = (const float4*)d_in[0];
    float4*       out = (float4*)d_out;
    pe_add_kernel<<<SEQ_LEN, THREADS>>>(in, out);
}

// round 2
// speedup vs baseline: 1.0035x; 1.0035x over previous
#include <cuda_runtime.h>

// out[b, s, d] = in[b, s, d] + PE[s, d]
// PE[s, 2i]   = sin(s / 10000^(2i/1024)),  PE[s, 2i+1] = cos(...)
//
// B=8, S=4096, D=1024, fp32 — 268 MB pure stream.
// R2 changes vs R1 (37.3us kernel, DRAM 72.8%):
//  - __ldcs/__stcs streaming (evict-first) hints: zero-reuse stream should
//    not occupy L2 (268MB working set vs 126MB L2).
//  - 2-deep software pipeline over the batch loop: prefetch load b+1
//    before storing b -> 2x per-thread MLP.
//  - 32-bit indexing (max idx 8.4M float4 << 2^31): kills IMAD.WIDE chains.

#define SEQ_LEN 4096
#define D_MODEL 1024
#define BATCH   8
#define THREADS 256   // 256 threads * float4 = 1024 floats = one PE row

__global__ void __launch_bounds__(THREADS, 8)
pe_add_kernel(const float4* __restrict__ in, float4* __restrict__ out) {
    const int pos = blockIdx.x;        // sequence position 0..4095
    const int t   = threadIdx.x;       // float4 index within row 0..255

    // PE for this thread's float4 (dims 4t..4t+3), computed once, reused 8x.
    const float LOG2_10000 = 13.287712379549449f;
    const float fpos = (float)pos;

    float e0 = (float)(4 * t)     * (1.0f / 1024.0f);
    float e1 = (float)(4 * t + 2) * (1.0f / 1024.0f);
    float a0 = fpos / exp2f(e0 * LOG2_10000);
    float a1 = fpos / exp2f(e1 * LOG2_10000);

    float s0, c0, s1, c1;
    sincosf(a0, &s0, &c0);   // accurate variant: angles reach ~4095 rad
    sincosf(a1, &s1, &c1);

    const float4 pe = make_float4(s0, c0, s1, c1);

    // 32-bit element offsets in float4 units.
    const int row_f4       = D_MODEL / 4;            // 256
    const int batch_stride = SEQ_LEN * row_f4;       // 1,048,576
    int idx = pos * row_f4 + t;

    // 2-deep pipeline: keep the next batch's load in flight while storing.
    float4 cur = __ldcs(in + idx);
#pragma unroll
    for (int b = 0; b < BATCH; ++b) {
        int next_idx = idx + batch_stride;
        float4 nxt;
        if (b < BATCH - 1) nxt = __ldcs(in + next_idx);
        float4 v = cur;
        v.x += pe.x;
        v.y += pe.y;
        v.z += pe.z;
        v.w += pe.w;
        __stcs(out + idx, v);
        cur = nxt;
        idx = next_idx;
    }
}

extern "C" void kernel_launch(void* const* d_in, const int* in_sizes, int n_in,
                              void* d_out, int out_size) {
    const float4* in  = (const float4*)d_in[0];
    float4*       out = (float4*)d_out;
    pe_add_kernel<<<SEQ_LEN, THREADS>>>(in, out);
}